// round 13
// baseline (speedup 1.0000x reference)
#include <cuda_runtime.h>
#include <cuda_bf16.h>

// Problem constants (match reference)
#define N_MOL   8
#define MA      24
#define DESIGN  26
#define RADIAL  15
#define MS      (RADIAL * DESIGN)        // 390 samples per atom
#define MXP     (MA * MS)                // 9360 grid points per molecule
#define RM_C    5.0f
#define PI_F    3.14159265358979323846f

// Output layout: concat(grid [N,MXP,3], dv [N,MXP,MA,3], weights [N,MXP])
#define GRID_FLOATS (N_MOL * MXP * 3)              // 224640
#define DV_OFF      GRID_FLOATS
#define DV_FLOATS   (N_MOL * MXP * MA * 3)         // 5391360
#define W_OFF       (DV_OFF + DV_FLOATS)           // 5616000

#define NROWS        (N_MOL * MXP)                 // 74880 grid points total
#define DV_BLOCKS    288
#define ROWS_PER_DVB (NROWS / DV_BLOCKS)           // 260 exactly

// Becke block mix per molecule (R10 mix, best profile): 77 split blocks
// (64 pts, 2 warps share a 32-point group) + 35 unsplit blocks (128 pts).
// 8*112 = 896 becke + 288 dv = 1184 = exactly 8/SM * 148 SMs -> ONE wave.
#define SPLIT_PER_MOL   77
#define UNSPLIT_PER_MOL 35
#define BK_PER_MOL      112
#define BECKE_BLOCKS    (N_MOL * BK_PER_MOL)       // 896
#define SPLIT_PTS       (SPLIT_PER_MOL * 64)       // 4928

typedef unsigned long long u64;

// ---- packed f32x2 helpers (Blackwell sm_100+) ----
__device__ __forceinline__ u64 pk(float lo, float hi) {
    u64 r; asm("mov.b64 %0, {%1, %2};" : "=l"(r) : "f"(lo), "f"(hi)); return r;
}
__device__ __forceinline__ void upk(u64 v, float& lo, float& hi) {
    asm("mov.b64 {%0, %1}, %2;" : "=f"(lo), "=f"(hi) : "l"(v));
}
__device__ __forceinline__ u64 fma2(u64 a, u64 b, u64 c) {
    u64 r; asm("fma.rn.f32x2 %0, %1, %2, %3;" : "=l"(r) : "l"(a), "l"(b), "l"(c)); return r;
}
__device__ __forceinline__ u64 mul2(u64 a, u64 b) {
    u64 r; asm("mul.rn.f32x2 %0, %1, %2;" : "=l"(r) : "l"(a), "l"(b)); return r;
}
__device__ __forceinline__ u64 add2(u64 a, u64 b) {
    u64 r; asm("add.rn.f32x2 %0, %1, %2;" : "=l"(r) : "l"(a), "l"(b)); return r;
}
__device__ __forceinline__ u64 swap2(u64 v) {        // (lo,hi) -> (hi,lo)
    float lo, hi; upk(v, lo, hi); return pk(hi, lo);
}
__device__ __forceinline__ u64 neg64(u64 v) {        // sign-flip both lanes (ALU)
    return v ^ 0x8000000080000000ULL;
}
__device__ __forceinline__ float rsqrt_a(float x) {
    float r; asm("rsqrt.approx.f32 %0, %1;" : "=f"(r) : "f"(x)); return r;
}

// Half the Becke tile set (parity of triangular index T), J-outer form.
// Per mu we stop softening BEFORE the final multiply: value is t1*w2, and
// (1 -/+ mu) are formed as fma2(-/+t1, w2, ONE) (negation = ALU sign-xor).
template<int SUB>
__device__ __forceinline__ void becke_tiles(const u64* rx2, u64* cell2,
                                            const ulonglong2 (*sAB)[12],
                                            u64 ONE, u64 C15, u64 CN05)
{
#pragma unroll
    for (int J = 0; J < 12; J++) {
        if ((J & 1) == SUB) {
            // diagonal pair (2J, 2J+1), scalar
            float rlo, rhi; upk(rx2[J], rlo, rhi);
            float mu = (rlo - rhi) * ((const float*)&sAB[J][J].y)[0];
            float m  = mu * mu;
            mu = mu * fmaf(m, -0.5f, 1.5f);
            m  = mu * mu;
            mu = mu * fmaf(m, -0.5f, 1.5f);
            cell2[J] = mul2(cell2[J], pk(1.0f - mu, 1.0f + mu));
        }
        if (J == 0) continue;

        const u64 rxJn  = neg64(rx2[J]);          // hoisted (ALU)
        const u64 rxJsn = neg64(swap2(rx2[J]));   // hoisted
        u64 accA = ONE;   // (1+muA) products: lane0 -> cell[2J]
        u64 accB = ONE;   // (1+muB) products: lane0 -> cell[2J+1] (swapped)

#pragma unroll
        for (int I = 0; I < J; I++) {
            const int T = I * 11 - (I * (I - 1)) / 2 + (J - I - 1);  // 0..65
            if ((T & 1) != SUB) continue;                            // constexpr

            const ulonglong2 ab = sAB[I][J];      // one LDS.128
            // aligned lanes: mu(2I,2J), mu(2I+1,2J+1)
            u64 tA = mul2(add2(rx2[I], rxJn),  ab.x);
            // cross lanes:   mu(2I,2J+1), mu(2I+1,2J)
            u64 tB = mul2(add2(rx2[I], rxJsn), ab.y);

            // softening pass 1 full, pass 2 without the final multiply
            u64 m2 = mul2(tA, tA);
            tA = mul2(tA, fma2(m2, CN05, C15));
            m2 = mul2(tA, tA);
            const u64 wA = fma2(m2, CN05, C15);   // muA = tA*wA (not formed)

            m2 = mul2(tB, tB);
            tB = mul2(tB, fma2(m2, CN05, C15));
            m2 = mul2(tB, tB);
            const u64 wB = fma2(m2, CN05, C15);   // muB = tB*wB (not formed)

            cell2[I] = mul2(cell2[I], fma2(neg64(tA), wA, ONE));  // 1-muA
            cell2[I] = mul2(cell2[I], fma2(neg64(tB), wB, ONE));  // 1-muB
            accA = mul2(accA, fma2(tA, wA, ONE));                 // 1+muA
            accB = mul2(accB, fma2(tB, wB, ONE));                 // 1+muB
        }
        cell2[J] = mul2(cell2[J], mul2(accA, swap2(accB)));
    }
}

// ============================================================================
// Block-role-specialized kernel, single-wave grid of 1184 blocks.
//   blocks [0, 288)     : grid + dv streaming stores (first -> full overlap)
//   blocks [288, 1184)  : Becke weights. Per molecule: 77 split blocks
//                         (2 warps per 32-point group, half tiles each,
//                         combined via shared) + 35 unsplit blocks.
// ============================================================================
__global__ __launch_bounds__(128, 8)
void grid_kernel(const float* __restrict__ coords,   // [N, MA, 3]
                 const float* __restrict__ sphere,   // [DESIGN, 3]
                 const float* __restrict__ sw,       // [DESIGN]
                 float* __restrict__ out)
{
    __shared__ float sph[DESIGN][3];
    __shared__ float r_tab[RADIAL];
    __shared__ float w_tab[RADIAL];
    // becke-only
    __shared__ float cs[MA][3];
    __shared__ float rdm_s[MA][MA];        // 1/max(dm,1e-12)
    __shared__ __align__(16) ulonglong2 sAB[12][12];
    __shared__ u64   scn[12][3];           // NEGATED packed coords
    __shared__ float sws[DESIGN];
    __shared__ u64   cstage[64][13];       // padded: conflict-free combine
    // dv-only
    __shared__ float g6[ROWS_PER_DVB][6];
    __shared__ short ns[ROWS_PER_DVB];

    const int tid = threadIdx.x;

    // common tables
    if (tid < DESIGN * 3) sph[tid / 3][tid % 3] = sphere[tid];
    if (tid < RADIAL) {
        float fi  = (float)(tid + 1);
        float z   = -cosf(PI_F * (2.0f * fi - 1.0f) / (2.0f * (float)RADIAL));
        float omz = 1.0f - z;
        float r   = RM_C * (1.0f + z) / omz;
        float dr  = 2.0f * RM_C / (omz * omz);
        float w   = sqrtf(1.0f - z * z) * dr * (PI_F / (float)RADIAL);
        r_tab[tid] = r;
        w_tab[tid] = r * r * 4.0f * PI_F * w;
    }

    if (blockIdx.x >= DV_BLOCKS) {
        // ================= Becke weights role =================
        const int b    = blockIdx.x - DV_BLOCKS;
        const int nmol = b / BK_PER_MOL;
        const int u    = b % BK_PER_MOL;
        const bool is_split = (u < SPLIT_PER_MOL);

        if (tid < MA * 3) cs[tid / 3][tid % 3] = coords[nmol * MA * 3 + tid];
        if (tid < DESIGN) sws[tid] = sw[tid];
        __syncthreads();

        for (int e = tid; e < MA * MA; e += 128) {
            int i = e / MA, j = e % MA;
            float dx = cs[i][0] - cs[j][0];
            float dy = cs[i][1] - cs[j][1];
            float dz = cs[i][2] - cs[j][2];
            float s2 = dx * dx + dy * dy + dz * dz;
            rdm_s[i][j] = rsqrt_a(fmaxf(s2, 1e-24f));   // 1/max(d,1e-12)
        }
        if (tid < 36) {
            int I = tid / 3, dd = tid % 3;
            scn[I][dd] = pk(-cs[2 * I][dd], -cs[2 * I + 1][dd]);
        }
        __syncthreads();
        for (int e = tid; e < 144; e += 128) {
            int I = e / 12, J = e % 12;
            ulonglong2 v;
            v.x = pk(rdm_s[2 * I][2 * J],     rdm_s[2 * I + 1][2 * J + 1]);
            v.y = pk(rdm_s[2 * I][2 * J + 1], rdm_s[2 * I + 1][2 * J]);
            sAB[I][J] = v;
        }
        __syncthreads();

        int ptl, pp, sub = 0, sub_mask;
        if (is_split) {
            const int warp = tid >> 5;
            sub  = warp & 1;                          // warp-uniform
            ptl  = (warp >> 1) * 32 + (tid & 31);     // 0..63
            pp   = u * 64 + ptl;
            sub_mask = 1 << sub;
        } else {
            ptl  = tid;
            pp   = SPLIT_PTS + (u - SPLIT_PER_MOL) * 128 + tid;
            sub_mask = 3;
        }
        const bool act = (pp < MXP);
        pp = min(pp, MXP - 1);                        // clamp for safe indexing

        const int am = pp / MS;
        const int k  = pp - am * MS;
        const int a  = k / DESIGN;
        const int d  = k - a * DESIGN;

        const float r  = r_tab[a];
        const float wt = sws[d] * w_tab[a];
        const float gx = cs[am][0] + r * sph[d][0];
        const float gy = cs[am][1] + r * sph[d][1];
        const float gz = cs[am][2] + r * sph[d][2];

        const u64 ONE  = pk(1.0f, 1.0f);
        const u64 C15  = pk(1.5f, 1.5f);
        const u64 CN05 = pk(-0.5f, -0.5f);

        const u64 gxx = pk(gx, gx), gyy = pk(gy, gy), gzz = pk(gz, gz);

        // distances, atom-packed; coords pre-negated -> add2 (rt2) not fma2
        u64 rx2[12];
#pragma unroll
        for (int I = 0; I < 12; I++) {
            u64 dx = add2(scn[I][0], gxx);
            u64 dy = add2(scn[I][1], gyy);
            u64 dz = add2(scn[I][2], gzz);
            u64 s  = mul2(dx, dx);
            s = fma2(dy, dy, s);
            s = fma2(dz, dz, s);
            float s0, s1; upk(s, s0, s1);
            rx2[I] = pk(s0 * rsqrt_a(s0), s1 * rsqrt_a(s1));
        }

        u64 cell2[12];
#pragma unroll
        for (int I = 0; I < 12; I++) cell2[I] = ONE;

        if (sub_mask & 1) becke_tiles<0>(rx2, cell2, sAB, ONE, C15, CN05);
        if (sub_mask & 2) becke_tiles<1>(rx2, cell2, sAB, ONE, C15, CN05);

        bool do_final = true;
        if (is_split) {
            // combine partial cell products across the warp pair
            if (sub == 1) {
#pragma unroll
                for (int I = 0; I < 12; I++) cstage[ptl][I] = cell2[I];
            }
            __syncthreads();
            if (sub == 0) {
#pragma unroll
                for (int I = 0; I < 12; I++)
                    cell2[I] = mul2(cell2[I], cstage[ptl][I]);
            } else {
                do_final = false;
            }
        }

        if (do_final) {
            u64 s2 = cell2[0];
#pragma unroll
            for (int I = 1; I < 12; I++) s2 = add2(s2, cell2[I]);
            float slo, shi; upk(s2, slo, shi);
            const float ssum = slo + shi;

            const int Iam = am >> 1;
            u64 cam2 = cell2[0];
#pragma unroll
            for (int I = 1; I < 12; I++) if (I == Iam) cam2 = cell2[I];
            float clo, chi; upk(cam2, clo, chi);
            const float cam = (am & 1) ? chi : clo;

            if (act)
                out[W_OFF + nmol * MXP + pp] = __fdividef(cam, ssum) * wt;
        }
    } else {
        // ================= grid + dv streaming role =================
        const int dvb = blockIdx.x;
        const int gp0 = dvb * ROWS_PER_DVB;
        __syncthreads();                           // tables ready

        // Phase A: grid coords for 260 rows -> grid section + shared staging
        for (int lp = tid; lp < ROWS_PER_DVB; lp += 128) {
            const int gp = gp0 + lp;
            const int n  = gp / MXP;
            const int p  = gp - n * MXP;
            const int am = p / MS;
            const int k  = p - am * MS;
            const int a  = k / DESIGN;
            const int d  = k - a * DESIGN;

            const float r = r_tab[a];
            const float* ca = coords + (n * MA + am) * 3;
            const float gx = __ldg(ca + 0) + r * sph[d][0];
            const float gy = __ldg(ca + 1) + r * sph[d][1];
            const float gz = __ldg(ca + 2) + r * sph[d][2];

            out[3 * gp + 0] = gx;
            out[3 * gp + 1] = gy;
            out[3 * gp + 2] = gz;

            g6[lp][0] = gx; g6[lp][1] = gy; g6[lp][2] = gz;
            g6[lp][3] = gx; g6[lp][4] = gy; g6[lp][5] = gz;
            ns[lp] = (short)n;
        }
        __syncthreads();

        // Phase B: dv stores, linear float4 stream (perfect coalescing).
        const float4* c4base = (const float4*)coords;   // 18 float4 per mol
        float4* dst4 = (float4*)(out + DV_OFF) + gp0 * 18;
        const int total4 = ROWS_PER_DVB * 18;           // 4680

        int lp = tid / 18;
        int rr = tid - lp * 18;
        for (int idx = tid; idx < total4; idx += 128) {
            const int rm = (rr >= 12) ? (rr - 12) % 3 : rr % 3;  // cheap mod
            const float pa = g6[lp][rm];
            const float pb = g6[lp][rm + 1];
            const float pc = g6[lp][rm + 2];
            const float4 c4 = __ldg(c4base + ns[lp] * 18 + rr);

            float4 o;
            o.x = pa - c4.x;
            o.y = pb - c4.y;
            o.z = pc - c4.z;
            o.w = pa - c4.w;
            dst4[idx] = o;

            lp += 7; rr += 2;
            if (rr >= 18) { rr -= 18; lp += 1; }
        }
    }
}

extern "C" void kernel_launch(void* const* d_in, const int* in_sizes, int n_in,
                              void* d_out, int out_size)
{
    // d_in[0]: labels (int32, unused -- padding is full for every molecule)
    const float* coords = (const float*)d_in[1];
    const float* sphere = (const float*)d_in[2];
    const float* sw     = (const float*)d_in[3];
    float* out = (float*)d_out;

    grid_kernel<<<DV_BLOCKS + BECKE_BLOCKS, 128>>>(coords, sphere, sw, out);
}

// round 14
// speedup vs baseline: 1.0328x; 1.0328x over previous
#include <cuda_runtime.h>
#include <cuda_bf16.h>

// Problem constants (match reference)
#define N_MOL   8
#define MA      24
#define DESIGN  26
#define RADIAL  15
#define MS      (RADIAL * DESIGN)        // 390 samples per atom
#define MXP     (MA * MS)                // 9360 grid points per molecule
#define RM_C    5.0f
#define PI_F    3.14159265358979323846f

// Output layout: concat(grid [N,MXP,3], dv [N,MXP,MA,3], weights [N,MXP])
#define GRID_FLOATS (N_MOL * MXP * 3)              // 224640
#define DV_OFF      GRID_FLOATS
#define DV_FLOATS   (N_MOL * MXP * MA * 3)         // 5391360
#define W_OFF       (DV_OFF + DV_FLOATS)           // 5616000

#define NROWS        (N_MOL * MXP)                 // 74880 grid points total
#define DV_BLOCKS    288
#define ROWS_PER_DVB (NROWS / DV_BLOCKS)           // 260 exactly

// Becke block mix per molecule (R10 mix, best measured profile): 77 split
// blocks (64 pts, 2 warps share a 32-point group) + 35 unsplit (128 pts).
// 8*112 = 896 becke + 288 dv = 1184 = exactly 8/SM * 148 SMs -> ONE wave.
#define SPLIT_PER_MOL   77
#define UNSPLIT_PER_MOL 35
#define BK_PER_MOL      112
#define BECKE_BLOCKS    (N_MOL * BK_PER_MOL)       // 896
#define SPLIT_PTS       (SPLIT_PER_MOL * 64)       // 4928

typedef unsigned long long u64;

// ---- packed f32x2 helpers (Blackwell sm_100+) ----
__device__ __forceinline__ u64 pk(float lo, float hi) {
    u64 r; asm("mov.b64 %0, {%1, %2};" : "=l"(r) : "f"(lo), "f"(hi)); return r;
}
__device__ __forceinline__ void upk(u64 v, float& lo, float& hi) {
    asm("mov.b64 {%0, %1}, %2;" : "=f"(lo), "=f"(hi) : "l"(v));
}
__device__ __forceinline__ u64 fma2(u64 a, u64 b, u64 c) {
    u64 r; asm("fma.rn.f32x2 %0, %1, %2, %3;" : "=l"(r) : "l"(a), "l"(b), "l"(c)); return r;
}
__device__ __forceinline__ u64 mul2(u64 a, u64 b) {
    u64 r; asm("mul.rn.f32x2 %0, %1, %2;" : "=l"(r) : "l"(a), "l"(b)); return r;
}
__device__ __forceinline__ u64 add2(u64 a, u64 b) {
    u64 r; asm("add.rn.f32x2 %0, %1, %2;" : "=l"(r) : "l"(a), "l"(b)); return r;
}
__device__ __forceinline__ u64 swap2(u64 v) {        // (lo,hi) -> (hi,lo)
    float lo, hi; upk(v, lo, hi); return pk(hi, lo);
}
__device__ __forceinline__ float rsqrt_a(float x) {
    float r; asm("rsqrt.approx.f32 %0, %1;" : "=f"(r) : "f"(x)); return r;
}

// Half the Becke tile set, chosen by triangular-index parity (compile-time).
// SUB=0: even tiles + even diagonals; SUB=1: odd tiles + odd diagonals.
// (R10's validated best-measured form -- unchanged.)
template<int SUB>
__device__ __forceinline__ void becke_tiles(const u64* rx2, u64* cell2,
                                            const ulonglong2 (*sAB)[12],
                                            u64 NEG1, u64 ONE, u64 C15, u64 CN05)
{
#pragma unroll
    for (int I = 0; I < 12; I++) {
        if ((I & 1) == SUB) {
            // diagonal pair (2I, 2I+1), scalar
            float rlo, rhi; upk(rx2[I], rlo, rhi);
            float mu = (rlo - rhi) * ((const float*)&sAB[I][I].y)[0];
            float m  = mu * mu;
            mu = mu * fmaf(m, -0.5f, 1.5f);
            m  = mu * mu;
            mu = mu * fmaf(m, -0.5f, 1.5f);
            cell2[I] = mul2(cell2[I], pk(1.0f - mu, 1.0f + mu));
        }
#pragma unroll
        for (int J = I + 1; J < 12; J++) {
            const int T = I * 11 - (I * (I - 1)) / 2 + (J - I - 1);  // 0..65
            if ((T & 1) != SUB) continue;                            // constexpr

            const ulonglong2 ab = sAB[I][J];   // one LDS.128
            u64 muA = mul2(fma2(rx2[J], NEG1, rx2[I]), ab.x);
            u64 muB = mul2(fma2(swap2(rx2[J]), NEG1, rx2[I]), ab.y);

            u64 m2 = mul2(muA, muA);
            muA = mul2(muA, fma2(m2, CN05, C15));
            m2  = mul2(muA, muA);
            muA = mul2(muA, fma2(m2, CN05, C15));

            m2  = mul2(muB, muB);
            muB = mul2(muB, fma2(m2, CN05, C15));
            m2  = mul2(muB, muB);
            muB = mul2(muB, fma2(m2, CN05, C15));

            cell2[I] = mul2(cell2[I], fma2(muA, NEG1, ONE));
            cell2[I] = mul2(cell2[I], fma2(muB, NEG1, ONE));
            cell2[J] = mul2(cell2[J], add2(muA, ONE));
            cell2[J] = mul2(cell2[J], add2(swap2(muB), ONE));
        }
    }
}

// ============================================================================
// Block-role-specialized kernel, single-wave grid of 1184 blocks.
//   blocks [0, 288)     : grid + dv streaming stores (first -> full overlap)
//   blocks [288, 1184)  : Becke weights. Per molecule: 77 split blocks
//                         (2 warps per 32-point group, half tiles each,
//                         combined via shared) + 35 unsplit blocks.
// Only change vs the best-measured R10: distance loop uses pre-NEGATED
// shared coords + add2 (2 distinct operands, RF-bank rt 2) instead of
// fma2(scp, NEG1, g) (3 distinct operands, rt 3).
// ============================================================================
__global__ __launch_bounds__(128, 8)
void grid_kernel(const float* __restrict__ coords,   // [N, MA, 3]
                 const float* __restrict__ sphere,   // [DESIGN, 3]
                 const float* __restrict__ sw,       // [DESIGN]
                 float* __restrict__ out)
{
    __shared__ float sph[DESIGN][3];
    __shared__ float r_tab[RADIAL];
    __shared__ float w_tab[RADIAL];
    // becke-only
    __shared__ float cs[MA][3];
    __shared__ float rdm_s[MA][MA];        // 1/max(dm,1e-12)
    __shared__ __align__(16) ulonglong2 sAB[12][12];
    __shared__ u64   scn[12][3];           // NEGATED packed coords
    __shared__ float sws[DESIGN];
    __shared__ u64   cstage[64][13];       // padded: conflict-free combine
    // dv-only
    __shared__ float g6[ROWS_PER_DVB][6];
    __shared__ short ns[ROWS_PER_DVB];

    const int tid = threadIdx.x;

    // common tables
    if (tid < DESIGN * 3) sph[tid / 3][tid % 3] = sphere[tid];
    if (tid < RADIAL) {
        float fi  = (float)(tid + 1);
        float z   = -cosf(PI_F * (2.0f * fi - 1.0f) / (2.0f * (float)RADIAL));
        float omz = 1.0f - z;
        float r   = RM_C * (1.0f + z) / omz;
        float dr  = 2.0f * RM_C / (omz * omz);
        float w   = sqrtf(1.0f - z * z) * dr * (PI_F / (float)RADIAL);
        r_tab[tid] = r;
        w_tab[tid] = r * r * 4.0f * PI_F * w;
    }

    if (blockIdx.x >= DV_BLOCKS) {
        // ================= Becke weights role =================
        const int b    = blockIdx.x - DV_BLOCKS;
        const int nmol = b / BK_PER_MOL;
        const int u    = b % BK_PER_MOL;
        const bool is_split = (u < SPLIT_PER_MOL);

        if (tid < MA * 3) cs[tid / 3][tid % 3] = coords[nmol * MA * 3 + tid];
        if (tid < DESIGN) sws[tid] = sw[tid];
        __syncthreads();

        for (int e = tid; e < MA * MA; e += 128) {
            int i = e / MA, j = e % MA;
            float dx = cs[i][0] - cs[j][0];
            float dy = cs[i][1] - cs[j][1];
            float dz = cs[i][2] - cs[j][2];
            float s2 = dx * dx + dy * dy + dz * dz;
            // 1/max(d,1e-12); s2=0 (i==j) -> huge, matches reference clip
            rdm_s[i][j] = rsqrt_a(fmaxf(s2, 1e-24f));
        }
        if (tid < 36) {
            int I = tid / 3, dd = tid % 3;
            scn[I][dd] = pk(-cs[2 * I][dd], -cs[2 * I + 1][dd]);
        }
        __syncthreads();
        for (int e = tid; e < 144; e += 128) {
            int I = e / 12, J = e % 12;
            ulonglong2 v;
            v.x = pk(rdm_s[2 * I][2 * J],     rdm_s[2 * I + 1][2 * J + 1]);
            v.y = pk(rdm_s[2 * I][2 * J + 1], rdm_s[2 * I + 1][2 * J]);
            sAB[I][J] = v;
        }
        __syncthreads();

        int ptl, pp, sub = 0, sub_mask;
        if (is_split) {
            const int warp = tid >> 5;
            sub  = warp & 1;                          // warp-uniform
            ptl  = (warp >> 1) * 32 + (tid & 31);     // 0..63
            pp   = u * 64 + ptl;
            sub_mask = 1 << sub;
        } else {
            ptl  = tid;
            pp   = SPLIT_PTS + (u - SPLIT_PER_MOL) * 128 + tid;
            sub_mask = 3;
        }
        const bool act = (pp < MXP);
        pp = min(pp, MXP - 1);                        // clamp for safe indexing

        const int am = pp / MS;
        const int k  = pp - am * MS;
        const int a  = k / DESIGN;
        const int d  = k - a * DESIGN;

        const float r  = r_tab[a];
        const float wt = sws[d] * w_tab[a];
        const float gx = cs[am][0] + r * sph[d][0];
        const float gy = cs[am][1] + r * sph[d][1];
        const float gz = cs[am][2] + r * sph[d][2];

        const u64 NEG1 = pk(-1.0f, -1.0f);
        const u64 ONE  = pk(1.0f, 1.0f);
        const u64 C15  = pk(1.5f, 1.5f);
        const u64 CN05 = pk(-0.5f, -0.5f);

        const u64 gxx = pk(gx, gx), gyy = pk(gy, gy), gzz = pk(gz, gz);

        // distances, atom-packed; pre-negated coords -> add2 (rt 2)
        u64 rx2[12];
#pragma unroll
        for (int I = 0; I < 12; I++) {
            u64 dx = add2(scn[I][0], gxx);
            u64 dy = add2(scn[I][1], gyy);
            u64 dz = add2(scn[I][2], gzz);
            u64 s  = mul2(dx, dx);
            s = fma2(dy, dy, s);
            s = fma2(dz, dz, s);
            float s0, s1; upk(s, s0, s1);
            rx2[I] = pk(s0 * rsqrt_a(s0), s1 * rsqrt_a(s1));
        }

        u64 cell2[12];
#pragma unroll
        for (int I = 0; I < 12; I++) cell2[I] = ONE;

        if (sub_mask & 1) becke_tiles<0>(rx2, cell2, sAB, NEG1, ONE, C15, CN05);
        if (sub_mask & 2) becke_tiles<1>(rx2, cell2, sAB, NEG1, ONE, C15, CN05);

        bool do_final = true;
        if (is_split) {
            // combine partial cell products across the warp pair
            if (sub == 1) {
#pragma unroll
                for (int I = 0; I < 12; I++) cstage[ptl][I] = cell2[I];
            }
            __syncthreads();
            if (sub == 0) {
#pragma unroll
                for (int I = 0; I < 12; I++)
                    cell2[I] = mul2(cell2[I], cstage[ptl][I]);
            } else {
                do_final = false;
            }
        }

        if (do_final) {
            u64 s2 = cell2[0];
#pragma unroll
            for (int I = 1; I < 12; I++) s2 = add2(s2, cell2[I]);
            float slo, shi; upk(s2, slo, shi);
            const float ssum = slo + shi;

            const int Iam = am >> 1;
            u64 cam2 = cell2[0];
#pragma unroll
            for (int I = 1; I < 12; I++) if (I == Iam) cam2 = cell2[I];
            float clo, chi; upk(cam2, clo, chi);
            const float cam = (am & 1) ? chi : clo;

            if (act)
                out[W_OFF + nmol * MXP + pp] = __fdividef(cam, ssum) * wt;
        }
    } else {
        // ================= grid + dv streaming role =================
        const int dvb = blockIdx.x;
        const int gp0 = dvb * ROWS_PER_DVB;
        __syncthreads();                           // tables ready

        // Phase A: grid coords for 260 rows -> grid section + shared staging
        for (int lp = tid; lp < ROWS_PER_DVB; lp += 128) {
            const int gp = gp0 + lp;
            const int n  = gp / MXP;
            const int p  = gp - n * MXP;
            const int am = p / MS;
            const int k  = p - am * MS;
            const int a  = k / DESIGN;
            const int d  = k - a * DESIGN;

            const float r = r_tab[a];
            const float* ca = coords + (n * MA + am) * 3;
            const float gx = __ldg(ca + 0) + r * sph[d][0];
            const float gy = __ldg(ca + 1) + r * sph[d][1];
            const float gz = __ldg(ca + 2) + r * sph[d][2];

            out[3 * gp + 0] = gx;
            out[3 * gp + 1] = gy;
            out[3 * gp + 2] = gz;

            g6[lp][0] = gx; g6[lp][1] = gy; g6[lp][2] = gz;
            g6[lp][3] = gx; g6[lp][4] = gy; g6[lp][5] = gz;
            ns[lp] = (short)n;
        }
        __syncthreads();

        // Phase B: dv stores, linear float4 stream (perfect coalescing).
        const float4* c4base = (const float4*)coords;   // 18 float4 per mol
        float4* dst4 = (float4*)(out + DV_OFF) + gp0 * 18;
        const int total4 = ROWS_PER_DVB * 18;           // 4680

        int lp = tid / 18;
        int rr = tid - lp * 18;
        for (int idx = tid; idx < total4; idx += 128) {
            const int rm = (rr >= 12) ? (rr - 12) % 3 : rr % 3;  // cheap mod
            const float pa = g6[lp][rm];
            const float pb = g6[lp][rm + 1];
            const float pc = g6[lp][rm + 2];
            const float4 c4 = __ldg(c4base + ns[lp] * 18 + rr);

            float4 o;
            o.x = pa - c4.x;
            o.y = pb - c4.y;
            o.z = pc - c4.z;
            o.w = pa - c4.w;
            dst4[idx] = o;

            lp += 7; rr += 2;
            if (rr >= 18) { rr -= 18; lp += 1; }
        }
    }
}

extern "C" void kernel_launch(void* const* d_in, const int* in_sizes, int n_in,
                              void* d_out, int out_size)
{
    // d_in[0]: labels (int32, unused -- padding is full for every molecule)
    const float* coords = (const float*)d_in[1];
    const float* sphere = (const float*)d_in[2];
    const float* sw     = (const float*)d_in[3];
    float* out = (float*)d_out;

    grid_kernel<<<DV_BLOCKS + BECKE_BLOCKS, 128>>>(coords, sphere, sw, out);
}